// round 1
// baseline (speedup 1.0000x reference)
#include <cuda_runtime.h>
#include <math.h>

#define BATCH 8
#define SEQ 1370
#define DIM 1024
#define HEADS 16
#define HDIM 64
#define MROWS (BATCH * SEQ)   // 10960

// Scratch (allocation-free: device globals)
__device__ float g_q[BATCH * HEADS * SEQ * HDIM];   // [B,H,S,Dh]
__device__ float g_k[BATCH * HEADS * SEQ * HDIM];
__device__ float g_v[BATCH * HEADS * SEQ * HDIM];
__device__ float g_ctx[BATCH * SEQ * DIM];          // [B,S,D]

// ---------------------------------------------------------------------------
// Tiled GEMM: C[M,1024] = A[M,1024] @ W[1024,1024] + bias
// 64x64 tile, BK=16, 256 threads, 4x4 per thread.
// csel: 0/1/2 -> write to g_q/g_k/g_v in [B,H,S,Dh] layout
//       3     -> write to Cext in plain [M,N] layout
// asel: 0 -> use Aext, 1 -> use g_ctx
// ---------------------------------------------------------------------------
__global__ __launch_bounds__(256) void gemm_kernel(
    const float* __restrict__ Aext, const float* __restrict__ W,
    const float* __restrict__ bias, float* __restrict__ Cext,
    int asel, int csel)
{
    __shared__ float As[16][65];
    __shared__ float Bs[16][64];

    const float* A = (asel == 1) ? g_ctx : Aext;

    int tid = threadIdx.x;
    int tx = tid & 15;
    int ty = tid >> 4;
    int m0 = blockIdx.x * 64;
    int n0 = blockIdx.y * 64;

    float acc[4][4];
#pragma unroll
    for (int i = 0; i < 4; i++)
#pragma unroll
        for (int j = 0; j < 4; j++) acc[i][j] = 0.f;

    // A-load mapping: each thread loads one float4 per tile
    int lm  = tid >> 2;         // 0..63 (row within tile)
    int lk4 = (tid & 3) * 4;    // 0,4,8,12
    bool avalid = (m0 + lm) < MROWS;
    const float* Arow = A + (size_t)(m0 + lm) * DIM;

    // W-load mapping
    int lbk  = tid >> 4;        // 0..15
    int lbn4 = (tid & 15) * 4;  // 0..60

    for (int k0 = 0; k0 < DIM; k0 += 16) {
        float4 av = avalid ? *(const float4*)(Arow + k0 + lk4)
                           : make_float4(0.f, 0.f, 0.f, 0.f);
        As[lk4 + 0][lm] = av.x;
        As[lk4 + 1][lm] = av.y;
        As[lk4 + 2][lm] = av.z;
        As[lk4 + 3][lm] = av.w;

        float4 wv = *(const float4*)(W + (size_t)(k0 + lbk) * DIM + n0 + lbn4);
        *(float4*)&Bs[lbk][lbn4] = wv;

        __syncthreads();

#pragma unroll
        for (int k = 0; k < 16; k++) {
            float a[4], b[4];
#pragma unroll
            for (int i = 0; i < 4; i++) a[i] = As[k][ty * 4 + i];
#pragma unroll
            for (int j = 0; j < 4; j++) b[j] = Bs[k][tx * 4 + j];
#pragma unroll
            for (int i = 0; i < 4; i++)
#pragma unroll
                for (int j = 0; j < 4; j++) acc[i][j] += a[i] * b[j];
        }
        __syncthreads();
    }

    // Epilogue
#pragma unroll
    for (int i = 0; i < 4; i++) {
        int m = m0 + ty * 4 + i;
        if (m >= MROWS) continue;
#pragma unroll
        for (int j = 0; j < 4; j++) {
            int n = n0 + tx * 4 + j;
            float v = acc[i][j] + bias[n];
            if (csel <= 2) {
                float* dst = (csel == 0) ? g_q : (csel == 1) ? g_k : g_v;
                int b_idx = m / SEQ;
                int s_idx = m - b_idx * SEQ;
                int h = n >> 6;
                int d = n & 63;
                dst[(((size_t)(b_idx * HEADS + h)) * SEQ + s_idx) * HDIM + d] = v;
            } else {
                Cext[(size_t)m * DIM + n] = v;
            }
        }
    }
}

// ---------------------------------------------------------------------------
// Flash-style attention: per (b,h), tile of 64 q rows, stream K/V in 64-row
// tiles with online softmax. 256 threads (16x16), 4x4 scores / 4x4 O per thr.
// Writes context to g_ctx in [B,S,D] layout.
// ---------------------------------------------------------------------------
__global__ __launch_bounds__(256) void attn_kernel()
{
    extern __shared__ float sm[];
    float* Qs = sm;                 // [64][65]
    float* Ks = sm + 64 * 65;       // [64][65]
    float* Vs = sm + 2 * 64 * 65;   // [64][65]
    float* Ps = sm + 3 * 64 * 65;   // [64][65]

    int tid = threadIdx.x;
    int tx = tid & 15;
    int ty = tid >> 4;
    int bh = blockIdx.y;
    int b = bh >> 4;
    int h = bh & 15;
    int q0 = blockIdx.x * 64;

    const float* Qg = g_q + ((size_t)(b * HEADS + h)) * SEQ * HDIM;
    const float* Kg = g_k + ((size_t)(b * HEADS + h)) * SEQ * HDIM;
    const float* Vg = g_v + ((size_t)(b * HEADS + h)) * SEQ * HDIM;

    // Load Q tile (zero-pad rows beyond SEQ)
    for (int e = tid; e < 64 * 16; e += 256) {
        int r = e >> 4;
        int d4 = (e & 15) * 4;
        float4 v = make_float4(0.f, 0.f, 0.f, 0.f);
        if (q0 + r < SEQ) v = *(const float4*)(Qg + (size_t)(q0 + r) * HDIM + d4);
        Qs[r * 65 + d4 + 0] = v.x;
        Qs[r * 65 + d4 + 1] = v.y;
        Qs[r * 65 + d4 + 2] = v.z;
        Qs[r * 65 + d4 + 3] = v.w;
    }

    float m_i[4], l_i[4], o[4][4];
#pragma unroll
    for (int i = 0; i < 4; i++) {
        m_i[i] = -INFINITY;
        l_i[i] = 0.f;
#pragma unroll
        for (int j = 0; j < 4; j++) o[i][j] = 0.f;
    }

    const float scale = 0.125f;  // 1/sqrt(64)

    for (int k0 = 0; k0 < SEQ; k0 += 64) {
        __syncthreads();  // previous iter done reading Ks/Vs/Ps
        // Load K and V tiles
        for (int e = tid; e < 64 * 16; e += 256) {
            int r = e >> 4;
            int d4 = (e & 15) * 4;
            float4 kv = make_float4(0.f, 0.f, 0.f, 0.f);
            float4 vv = make_float4(0.f, 0.f, 0.f, 0.f);
            if (k0 + r < SEQ) {
                kv = *(const float4*)(Kg + (size_t)(k0 + r) * HDIM + d4);
                vv = *(const float4*)(Vg + (size_t)(k0 + r) * HDIM + d4);
            }
            Ks[r * 65 + d4 + 0] = kv.x; Ks[r * 65 + d4 + 1] = kv.y;
            Ks[r * 65 + d4 + 2] = kv.z; Ks[r * 65 + d4 + 3] = kv.w;
            Vs[r * 65 + d4 + 0] = vv.x; Vs[r * 65 + d4 + 1] = vv.y;
            Vs[r * 65 + d4 + 2] = vv.z; Vs[r * 65 + d4 + 3] = vv.w;
        }
        __syncthreads();

        // S = Q @ K^T (4x4 per thread)
        float s[4][4];
#pragma unroll
        for (int i = 0; i < 4; i++)
#pragma unroll
            for (int j = 0; j < 4; j++) s[i][j] = 0.f;

#pragma unroll 8
        for (int d = 0; d < 64; d++) {
            float a[4], kb[4];
#pragma unroll
            for (int i = 0; i < 4; i++) a[i] = Qs[(ty * 4 + i) * 65 + d];
#pragma unroll
            for (int j = 0; j < 4; j++) kb[j] = Ks[(tx * 4 + j) * 65 + d];
#pragma unroll
            for (int i = 0; i < 4; i++)
#pragma unroll
                for (int j = 0; j < 4; j++) s[i][j] += a[i] * kb[j];
        }

        // scale + mask invalid k columns
#pragma unroll
        for (int j = 0; j < 4; j++) {
            bool valid = (k0 + tx * 4 + j) < SEQ;
#pragma unroll
            for (int i = 0; i < 4; i++)
                s[i][j] = valid ? s[i][j] * scale : -INFINITY;
        }

        // Online softmax update per row (reduce over 16 lanes sharing a row)
#pragma unroll
        for (int i = 0; i < 4; i++) {
            float rmax = s[i][0];
#pragma unroll
            for (int j = 1; j < 4; j++) rmax = fmaxf(rmax, s[i][j]);
#pragma unroll
            for (int off = 8; off >= 1; off >>= 1)
                rmax = fmaxf(rmax, __shfl_xor_sync(0xffffffffu, rmax, off, 16));

            float mn = fmaxf(m_i[i], rmax);
            float alpha = __expf(m_i[i] - mn);
            m_i[i] = mn;

            float rsum = 0.f;
#pragma unroll
            for (int j = 0; j < 4; j++) {
                float p = __expf(s[i][j] - mn);
                s[i][j] = p;
                rsum += p;
            }
#pragma unroll
            for (int off = 8; off >= 1; off >>= 1)
                rsum += __shfl_xor_sync(0xffffffffu, rsum, off, 16);

            l_i[i] = l_i[i] * alpha + rsum;
#pragma unroll
            for (int j = 0; j < 4; j++) o[i][j] *= alpha;
            // stage P tile
#pragma unroll
            for (int j = 0; j < 4; j++)
                Ps[(ty * 4 + i) * 65 + tx * 4 + j] = s[i][j];
        }
        __syncthreads();

        // O += P @ V
#pragma unroll 8
        for (int kk = 0; kk < 64; kk++) {
            float p[4], vv[4];
#pragma unroll
            for (int i = 0; i < 4; i++) p[i] = Ps[(ty * 4 + i) * 65 + kk];
#pragma unroll
            for (int j = 0; j < 4; j++) vv[j] = Vs[kk * 65 + tx * 4 + j];
#pragma unroll
            for (int i = 0; i < 4; i++)
#pragma unroll
                for (int j = 0; j < 4; j++) o[i][j] += p[i] * vv[j];
        }
    }

    // Epilogue: normalize and write context in [B,S,D] layout
#pragma unroll
    for (int i = 0; i < 4; i++) {
        int q = q0 + ty * 4 + i;
        if (q >= SEQ) continue;
        float inv = 1.f / l_i[i];
#pragma unroll
        for (int j = 0; j < 4; j++) {
            g_ctx[((size_t)(b * SEQ + q)) * DIM + h * HDIM + tx * 4 + j] = o[i][j] * inv;
        }
    }
}

// ---------------------------------------------------------------------------
extern "C" void kernel_launch(void* const* d_in, const int* in_sizes, int n_in,
                              void* d_out, int out_size)
{
    const float* x  = (const float*)d_in[0];
    const float* Wq = (const float*)d_in[1];
    const float* bq = (const float*)d_in[2];
    const float* Wk = (const float*)d_in[3];
    const float* bk = (const float*)d_in[4];
    const float* Wv = (const float*)d_in[5];
    const float* bv = (const float*)d_in[6];
    const float* Wo = (const float*)d_in[7];
    const float* bo = (const float*)d_in[8];
    float* out = (float*)d_out;

    dim3 gemmGrid((MROWS + 63) / 64, DIM / 64);  // 172 x 16

    // Q/K/V projections
    gemm_kernel<<<gemmGrid, 256>>>(x, Wq, bq, nullptr, 0, 0);
    gemm_kernel<<<gemmGrid, 256>>>(x, Wk, bk, nullptr, 0, 1);
    gemm_kernel<<<gemmGrid, 256>>>(x, Wv, bv, nullptr, 0, 2);

    // Attention
    int smem = 4 * 64 * 65 * sizeof(float);  // 66560
    cudaFuncSetAttribute(attn_kernel, cudaFuncAttributeMaxDynamicSharedMemorySize, smem);
    dim3 attnGrid((SEQ + 63) / 64, BATCH * HEADS);  // 22 x 128
    attn_kernel<<<attnGrid, 256, smem>>>();

    // Output projection: out = g_ctx @ Wo + bo
    gemm_kernel<<<gemmGrid, 256>>>(nullptr, Wo, bo, out, 1, 3);
}